// round 8
// baseline (speedup 1.0000x reference)
#include <cuda_runtime.h>
#include <cuda_bf16.h>

// x: [B=16, C=64, H=256, W=256] fp32; conv_w [1,2,7,7]; conv_b [1]
// out = x * sigmoid(conv7x7(concat(mean_c(x), max_c(x))) + b)
//
// Chunked L2 staging: process 4 batches (64 MB of x) at a time.
//   K1 reduce reads x[chunk] with DEFAULT caching -> chunk resident in L2.
//   K2 conv (tiny).
//   K3 mul re-reads x[chunk] as L2 hits (ldcs: evict after use) and streams
//      out with stcs. DRAM sees x once + out once.

#define B 16
#define C 64
#define HW 65536           // 256*256
#define HWf4 16384         // HW/4
#define PLANE (C * HW)     // 2^22 elements (16 MB)
#define NBCH 4             // batches per chunk (64 MB of x)

__device__ float g_att[B * 2 * HW];   // [b][{avg,max}][hw]
__device__ float g_s[B * HW];

// ---------------------------------------------------------------------------
// K1: per-pixel channel mean+max for NBCH batches starting at b0.
// One thread = one float4-pixel, 64 channels. Default-cached loads so the
// chunk stays L2-resident for K3.
// ---------------------------------------------------------------------------
__global__ void k_reduce(const float* __restrict__ x, int b0) {
    int t = blockIdx.x * blockDim.x + threadIdx.x;        // [0, NBCH*HWf4)
    int b  = b0 + (t >> 14);
    int q4 = t & (HWf4 - 1);

    const float4* xb = reinterpret_cast<const float4*>(x + (size_t)b * PLANE);

    float4 v = xb[q4];                                     // c = 0 (cached)
    float sx = v.x, sy = v.y, sz = v.z, sw = v.w;
    float mx = v.x, my = v.y, mz = v.z, mw = v.w;

#pragma unroll 8
    for (int c = 1; c < C; c++) {
        float4 u = xb[(size_t)c * HWf4 + q4];
        sx += u.x; sy += u.y; sz += u.z; sw += u.w;
        mx = fmaxf(mx, u.x); my = fmaxf(my, u.y);
        mz = fmaxf(mz, u.z); mw = fmaxf(mw, u.w);
    }

    const float inv = 1.0f / 64.0f;
    float4* avg_out = reinterpret_cast<float4*>(g_att + (size_t)b * 2 * HW);
    float4* max_out = reinterpret_cast<float4*>(g_att + (size_t)b * 2 * HW + HW);
    avg_out[q4] = make_float4(sx * inv, sy * inv, sz * inv, sw * inv);
    max_out[q4] = make_float4(mx, my, mz, mw);
}

// ---------------------------------------------------------------------------
// K2: 7x7 conv + bias + sigmoid -> g_s. 64x16 tile, register sliding window.
// Grid: (4, 16, NBCH), 256 threads. Thread owns 4 outputs in w.
// ---------------------------------------------------------------------------
__global__ void k_conv(const float* __restrict__ cw, const float* __restrict__ cb,
                       int b0) {
    __shared__ float s_avg[22 * 72];
    __shared__ float s_mx[22 * 72];
    __shared__ float s_w[98];
    __shared__ float s_b;

    const int b  = b0 + blockIdx.z;
    const int w0 = blockIdx.x * 64;
    const int h0 = blockIdx.y * 16;
    const int tid = threadIdx.x;

    if (tid < 98) s_w[tid] = cw[tid];
    if (tid == 98) s_b = cb[0];

    const float* avgp = g_att + (size_t)b * 2 * HW;
    const float* maxp = avgp + HW;

    for (int i = tid; i < 22 * 70; i += 256) {
        int dy = i / 70, dx = i - dy * 70;
        int hh = h0 - 3 + dy, ww = w0 - 3 + dx;
        float a = 0.f, m = 0.f;
        if (hh >= 0 && hh < 256 && ww >= 0 && ww < 256) {
            int ii = hh * 256 + ww;
            a = avgp[ii];
            m = maxp[ii];
        }
        s_avg[dy * 72 + dx] = a;
        s_mx[dy * 72 + dx]  = m;
    }
    __syncthreads();

    const int tx = tid & 15;
    const int ty = tid >> 4;
    const int ow0 = tx * 4;

    float a0 = s_b, a1 = a0, a2 = a0, a3 = a0;
#pragma unroll
    for (int kh = 0; kh < 7; kh++) {
        const float* ra = s_avg + (ty + kh) * 72 + ow0;
        const float* rm = s_mx  + (ty + kh) * 72 + ow0;
        float v[10];
#pragma unroll
        for (int j = 0; j < 10; j++) v[j] = ra[j];
#pragma unroll
        for (int kw = 0; kw < 7; kw++) {
            float wA = s_w[kh * 7 + kw];
            a0 = fmaf(wA, v[kw],     a0);
            a1 = fmaf(wA, v[kw + 1], a1);
            a2 = fmaf(wA, v[kw + 2], a2);
            a3 = fmaf(wA, v[kw + 3], a3);
        }
#pragma unroll
        for (int j = 0; j < 10; j++) v[j] = rm[j];
#pragma unroll
        for (int kw = 0; kw < 7; kw++) {
            float wM = s_w[49 + kh * 7 + kw];
            a0 = fmaf(wM, v[kw],     a0);
            a1 = fmaf(wM, v[kw + 1], a1);
            a2 = fmaf(wM, v[kw + 2], a2);
            a3 = fmaf(wM, v[kw + 3], a3);
        }
    }
    float4 sg;
    sg.x = 1.0f / (1.0f + __expf(-a0));
    sg.y = 1.0f / (1.0f + __expf(-a1));
    sg.z = 1.0f / (1.0f + __expf(-a2));
    sg.w = 1.0f / (1.0f + __expf(-a3));
    *reinterpret_cast<float4*>(g_s + (size_t)b * HW + (h0 + ty) * 256 + w0 + ow0) = sg;
}

// ---------------------------------------------------------------------------
// K3: out = x * s for the chunk. One thread = 4 float4s, loads batched
// (MLP=8). x reads hit L2 (ldcs marks evict-after-use); out streams (stcs).
// ---------------------------------------------------------------------------
__global__ void k_mul(const float* __restrict__ x, float* __restrict__ out,
                      int b0) {
    const size_t chunk0 = (size_t)b0 << 20;                // f4 offset of chunk
    const size_t base = chunk0 + (size_t)blockIdx.x * 1024 + threadIdx.x;
    const int b = (int)(base >> 20);

    const float4* xf = reinterpret_cast<const float4*>(x);
    float4* of = reinterpret_cast<float4*>(out);
    const float4* sb = reinterpret_cast<const float4*>(g_s + (size_t)b * HW);

    float4 xv[4], sv[4];
#pragma unroll
    for (int k = 0; k < 4; k++) xv[k] = __ldcs(xf + base + k * 256);
#pragma unroll
    for (int k = 0; k < 4; k++) {
        int q4 = (int)((base + k * 256) & (HWf4 - 1));
        sv[k] = __ldg(sb + q4);
    }
#pragma unroll
    for (int k = 0; k < 4; k++) {
        xv[k].x *= sv[k].x; xv[k].y *= sv[k].y;
        xv[k].z *= sv[k].z; xv[k].w *= sv[k].w;
        __stcs(of + base + k * 256, xv[k]);
    }
}

// ---------------------------------------------------------------------------
extern "C" void kernel_launch(void* const* d_in, const int* in_sizes, int n_in,
                              void* d_out, int out_size) {
    const float* x  = (const float*)d_in[0];
    const float* cw = (const float*)d_in[1];
    const float* cb = (const float*)d_in[2];
    float* out = (float*)d_out;

    for (int b0 = 0; b0 < B; b0 += NBCH) {
        k_reduce<<<(NBCH * HWf4) / 256, 256>>>(x, b0);

        dim3 g2(4, 16, NBCH);
        k_conv<<<g2, 256>>>(cw, cb, b0);

        k_mul<<<(NBCH * (PLANE / 4)) / 1024, 256>>>(x, out, b0);
    }
}